// round 4
// baseline (speedup 1.0000x reference)
#include <cuda_runtime.h>

#define THREADS 256
#define BM 64
#define BK 32
#define HID 256
#define INCH 256

__global__ void __launch_bounds__(THREADS, 2)
edge_decoder_kernel(const float* __restrict__ z,
                    const int* __restrict__ src,
                    const int* __restrict__ dst,
                    const float* __restrict__ W1,
                    const float* __restrict__ b1,
                    const float* __restrict__ W2,
                    const float* __restrict__ b2,
                    float* __restrict__ out,
                    int E, int Nn)
{
    __shared__ __align__(16) float xs[BM][BK];     // gathered x tile (8 KB)
    __shared__ __align__(16) float ws[BK][HID];    // W1 tile (32 KB)
    __shared__ int soff[BM];
    __shared__ int doff[BM];
    __shared__ float s_b1[HID];
    __shared__ float s_w2[HID];

    const int tid  = threadIdx.x;
    const int warp = tid >> 5;   // 8 warps; warp w owns edges w*8..w*8+7
    const int lane = tid & 31;
    const long long e0 = (long long)blockIdx.x * BM;

    if (tid < BM) {
        long long e = e0 + tid;
        if (e >= E) e = E - 1;
        int s = src[e];
        int d = dst[e];
        // defensive clamp: keeps gather addresses in-bounds no matter what
        s = (s < 0) ? 0 : (s >= Nn ? Nn - 1 : s);
        d = (d < 0) ? 0 : (d >= Nn ? Nn - 1 : d);
        soff[tid] = s * INCH;
        doff[tid] = d * INCH;
    }
    s_b1[tid] = b1[tid];   // THREADS == HID == 256
    s_w2[tid] = W2[tid];

    // 8 edges x 4 column-pair-groups, each float2 => 64 fp32 accumulators
    float2 acc[8][4];
    #pragma unroll
    for (int r = 0; r < 8; r++)
        #pragma unroll
        for (int g = 0; g < 4; g++) acc[r][g] = make_float2(0.f, 0.f);

    for (int k0 = 0; k0 < INCH; k0 += BK) {
        __syncthreads();   // previous-iter readers done (also covers preload)

        // Gather x tile: 64 edges x 32 k = 512 float4 loads, 2 per thread.
        #pragma unroll
        for (int j = 0; j < 2; j++) {
            int q  = tid + j * THREADS;        // 0..511
            int r  = q >> 3;                   // edge row 0..63
            int kk = (q & 7) << 2;             // k offset 0..28
            float4 a = *(const float4*)(z + soff[r] + k0 + kk);
            float4 b = *(const float4*)(z + doff[r] + k0 + kk);
            float4 p;
            p.x = a.x * b.x; p.y = a.y * b.y; p.z = a.z * b.z; p.w = a.w * b.w;
            *(float4*)(&xs[r][kk]) = p;
        }

        // Load W1 tile: 32 x 256 floats = 2048 float4, 8 per thread, coalesced.
        #pragma unroll
        for (int j = 0; j < 8; j++) {
            int q  = tid + j * THREADS;        // 0..2047
            int kr = q >> 6;                   // row 0..31
            int c4 = (q & 63) << 2;            // col 0..252
            *(float4*)(&ws[kr][c4]) = *(const float4*)(W1 + (k0 + kr) * HID + c4);
        }
        __syncthreads();

        // Compute: per k, per lane load 4 float2 column-pairs of W1
        // (8-byte LDS, half-warp spans all 32 banks -> conflict-free),
        // broadcast x from shared, 64 FFMA per thread.
        #pragma unroll
        for (int k = 0; k < BK; k++) {
            const float2* wr = (const float2*)(&ws[k][0]);
            float2 w0 = wr[lane];        // cols   2l,   2l+1
            float2 w1 = wr[32 + lane];   // cols  64+2l
            float2 w2v = wr[64 + lane];  // cols 128+2l
            float2 w3 = wr[96 + lane];   // cols 192+2l
            #pragma unroll
            for (int r = 0; r < 8; r++) {
                float a = xs[warp * 8 + r][k];  // broadcast LDS
                acc[r][0].x = fmaf(a, w0.x, acc[r][0].x);
                acc[r][0].y = fmaf(a, w0.y, acc[r][0].y);
                acc[r][1].x = fmaf(a, w1.x, acc[r][1].x);
                acc[r][1].y = fmaf(a, w1.y, acc[r][1].y);
                acc[r][2].x = fmaf(a, w2v.x, acc[r][2].x);
                acc[r][2].y = fmaf(a, w2v.y, acc[r][2].y);
                acc[r][3].x = fmaf(a, w3.x, acc[r][3].x);
                acc[r][3].y = fmaf(a, w3.y, acc[r][3].y);
            }
        }
    }

    // Fused epilogue: h = relu(acc + b1); partial = h . W2 ; warp-reduce; sigmoid.
    float bias2 = b2[0];
    #pragma unroll
    for (int r = 0; r < 8; r++) {
        float p = 0.f;
        #pragma unroll
        for (int g = 0; g < 4; g++) {
            int c = g * 64 + 2 * lane;
            float h0 = acc[r][g].x + s_b1[c];
            float h1 = acc[r][g].y + s_b1[c + 1];
            p = fmaf(fmaxf(h0, 0.f), s_w2[c], p);
            p = fmaf(fmaxf(h1, 0.f), s_w2[c + 1], p);
        }
        #pragma unroll
        for (int o = 16; o > 0; o >>= 1)
            p += __shfl_xor_sync(0xffffffffu, p, o);
        if (lane == 0) {
            long long e = e0 + warp * 8 + r;
            if (e < E)
                out[e] = 1.f / (1.f + __expf(-(p + bias2)));
        }
    }
}

extern "C" void kernel_launch(void* const* d_in, const int* in_sizes, int n_in,
                              void* d_out, int out_size) {
    // Input mapping by element count (confirmed consistent with dict order):
    //   z  : N*256   = 25,600,000 f32
    //   src: E       =  1,000,000 int32  (JAX default x64-disabled -> int32!)
    //   dst: E       =  1,000,000 int32  (src/dst symmetric in the product)
    //   W1 : 256*256 =     65,536 f32
    //   b1 : 256 f32, W2 : 256 f32  (dict order: b1 first when z is input 0)
    //   b2 : 1 f32
    int idx_z = -1, idx_w1 = -1, idx_b2 = -1;
    int idx_e1 = -1, idx_e2 = -1;
    int idx_s1 = -1, idx_s2 = -1;
    for (int i = 0; i < n_in; i++) {
        int s = in_sizes[i];
        if (s == 25600000)      idx_z = i;
        else if (s == 65536)    idx_w1 = i;
        else if (s == 1)        idx_b2 = i;
        else if (s == 1000000) { if (idx_e1 < 0) idx_e1 = i; else idx_e2 = i; }
        else if (s == 256)     { if (idx_s1 < 0) idx_s1 = i; else idx_s2 = i; }
    }
    int idx_b1 = (idx_z == 0) ? idx_s1 : idx_s2;
    int idx_w2 = (idx_z == 0) ? idx_s2 : idx_s1;

    const float* z   = (const float*)d_in[idx_z];
    const int*   src = (const int*)d_in[idx_e1];
    const int*   dst = (const int*)d_in[idx_e2];
    const float* W1  = (const float*)d_in[idx_w1];
    const float* b1  = (const float*)d_in[idx_b1];
    const float* W2  = (const float*)d_in[idx_w2];
    const float* b2  = (const float*)d_in[idx_b2];
    float* out = (float*)d_out;

    int E  = in_sizes[idx_e1];                 // 1,000,000
    int Nn = in_sizes[idx_z] / INCH;           // 100,000 nodes
    int grid = (E + BM - 1) / BM;              // 15625 blocks
    edge_decoder_kernel<<<grid, THREADS>>>(z, src, dst, W1, b1, W2, b2, out, E, Nn);
}

// round 6
// speedup vs baseline: 2.2150x; 2.2150x over previous
#include <cuda_runtime.h>
#include <cuda_bf16.h>
#include <cstdint>

#define THREADS 256
#define BM 64            // edges per CTA
#define BK 64            // K chunk
#define HID 256
#define INCH 256
#define NCHUNK (INCH / BK)      // 4
#define AROW 144         // 64 bf16 = 128B + 16B pad
#define BROW 144
#define A_HI 0
#define A_LO (A_HI + BM * AROW)                  //  9216
#define B_HI (A_LO + BM * AROW)                  // 18432
#define B_LO (B_HI + HID * BROW)                 // 55296
#define SMEM_DYN (B_LO + HID * BROW)             // 92160

// W1 transposed + bf16-split, K-major: [n][k]
__device__ __nv_bfloat16 g_W1T_hi[HID * INCH];
__device__ __nv_bfloat16 g_W1T_lo[HID * INCH];

__global__ void prep_w1(const float* __restrict__ W1) {
    int k = blockIdx.x;       // 0..255
    int n = threadIdx.x;      // 0..255
    float w = W1[k * HID + n];
    __nv_bfloat16 hi = __float2bfloat16(w);
    float lo = w - __bfloat162float(hi);
    g_W1T_hi[n * INCH + k] = hi;
    g_W1T_lo[n * INCH + k] = __float2bfloat16(lo);
}

static __device__ __forceinline__ void mma16816(float* d, const uint32_t* a,
                                                uint32_t b0, uint32_t b1) {
    asm volatile(
        "mma.sync.aligned.m16n8k16.row.col.f32.bf16.bf16.f32 "
        "{%0,%1,%2,%3},{%4,%5,%6,%7},{%8,%9},{%0,%1,%2,%3};"
        : "+f"(d[0]), "+f"(d[1]), "+f"(d[2]), "+f"(d[3])
        : "r"(a[0]), "r"(a[1]), "r"(a[2]), "r"(a[3]), "r"(b0), "r"(b1));
}

__global__ void __launch_bounds__(THREADS, 2)
edge_decoder_hmma(const float* __restrict__ z,
                  const int* __restrict__ src,
                  const int* __restrict__ dst,
                  const float* __restrict__ b1,
                  const float* __restrict__ W2,
                  const float* __restrict__ b2,
                  float* __restrict__ out,
                  int E, int Nn)
{
    extern __shared__ __align__(16) char sm[];
    __shared__ int soff[BM];
    __shared__ int doff[BM];
    __shared__ float s_b1[HID];
    __shared__ float s_w2[HID];
    __shared__ float s_part[BM][4];

    const int tid  = threadIdx.x;
    const int wid  = tid >> 5;
    const int lane = tid & 31;
    const int wm   = wid & 1;        // M half: edges wm*32..+32
    const int wn   = wid >> 1;       // N quarter: cols wn*64..+64
    const int g    = lane >> 2;      // fragment row group 0..7
    const int c4   = (lane & 3) << 2;  // byte offset of k-pair within row
    const long long e0 = (long long)blockIdx.x * BM;

    if (tid < BM) {
        long long e = e0 + tid;
        if (e >= E) e = E - 1;
        int s = src[e], d = dst[e];
        s = (s < 0) ? 0 : (s >= Nn ? Nn - 1 : s);
        d = (d < 0) ? 0 : (d >= Nn ? Nn - 1 : d);
        soff[tid] = s * INCH;
        doff[tid] = d * INCH;
    }
    s_b1[tid] = b1[tid];
    s_w2[tid] = W2[tid];

    // D accumulators: 2 m-tiles x 8 n-tiles x 4 regs = 64 fp32
    float d[2][8][4];
    #pragma unroll
    for (int mt = 0; mt < 2; mt++)
        #pragma unroll
        for (int nt = 0; nt < 8; nt++)
            #pragma unroll
            for (int i = 0; i < 4; i++) d[mt][nt][i] = 0.f;

    // per-thread fragment base offsets (within-tile, byte units)
    int aoff[2];
    #pragma unroll
    for (int mt = 0; mt < 2; mt++)
        aoff[mt] = (wm * 32 + mt * 16 + g) * AROW + c4;
    const int boff = (wn * 64 + g) * BROW + c4;

    for (int c = 0; c < NCHUNK; c++) {
        const int k0 = c * BK;
        __syncthreads();   // previous chunk fully consumed

        // ---- A tile: gather z, product, bf16 split ----
        // 64 edges x 64 k = 4096 f32 -> 1024 float4, 4 per thread.
        #pragma unroll
        for (int j = 0; j < 4; j++) {
            int q  = tid + j * THREADS;        // 0..1023
            int m  = q >> 4;                   // edge row
            int kl = (q & 15) << 2;            // local k, 16 threads cover the row
            const float4 a = *(const float4*)(z + soff[m] + k0 + kl);
            const float4 b = *(const float4*)(z + doff[m] + k0 + kl);
            float4 pr;
            pr.x = a.x * b.x; pr.y = a.y * b.y; pr.z = a.z * b.z; pr.w = a.w * b.w;
            __nv_bfloat162 h01 = __floats2bfloat162_rn(pr.x, pr.y);
            __nv_bfloat162 h23 = __floats2bfloat162_rn(pr.z, pr.w);
            float2 f01 = __bfloat1622float2(h01);
            float2 f23 = __bfloat1622float2(h23);
            __nv_bfloat162 l01 = __floats2bfloat162_rn(pr.x - f01.x, pr.y - f01.y);
            __nv_bfloat162 l23 = __floats2bfloat162_rn(pr.z - f23.x, pr.w - f23.y);
            uint2 hv, lv;
            hv.x = *(uint32_t*)&h01; hv.y = *(uint32_t*)&h23;
            lv.x = *(uint32_t*)&l01; lv.y = *(uint32_t*)&l23;
            int off = m * AROW + kl * 2;
            *(uint2*)(sm + A_HI + off) = hv;
            *(uint2*)(sm + A_LO + off) = lv;
        }

        // ---- B tiles: W1T [n][k0..k0+64) hi/lo, 128B per row, 8 uint4/row ----
        const char* gH = (const char*)g_W1T_hi;
        const char* gL = (const char*)g_W1T_lo;
        #pragma unroll
        for (int j = 0; j < 8; j++) {
            int q   = tid + j * THREADS;       // 0..2047
            int n   = q >> 3;
            int c16 = (q & 7) << 4;
            int goff = n * (INCH * 2) + k0 * 2 + c16;
            int off  = n * BROW + c16;
            *(uint4*)(sm + B_HI + off) = *(const uint4*)(gH + goff);
            *(uint4*)(sm + B_LO + off) = *(const uint4*)(gL + goff);
        }
        __syncthreads();

        // ---- compute: 4 k16 steps ----
        #pragma unroll
        for (int ks = 0; ks < BK / 16; ks++) {
            const int kb = ks * 32;            // 16 bf16 = 32 B
            uint32_t ah[2][4], al[2][4];
            #pragma unroll
            for (int mt = 0; mt < 2; mt++) {
                int base = aoff[mt] + kb;
                ah[mt][0] = *(const uint32_t*)(sm + A_HI + base);
                ah[mt][1] = *(const uint32_t*)(sm + A_HI + base + 8 * AROW);
                ah[mt][2] = *(const uint32_t*)(sm + A_HI + base + 16);
                ah[mt][3] = *(const uint32_t*)(sm + A_HI + base + 8 * AROW + 16);
                al[mt][0] = *(const uint32_t*)(sm + A_LO + base);
                al[mt][1] = *(const uint32_t*)(sm + A_LO + base + 8 * AROW);
                al[mt][2] = *(const uint32_t*)(sm + A_LO + base + 16);
                al[mt][3] = *(const uint32_t*)(sm + A_LO + base + 8 * AROW + 16);
            }
            #pragma unroll
            for (int nt = 0; nt < 8; nt++) {
                int bb = boff + nt * 8 * BROW + kb;
                uint32_t bh0 = *(const uint32_t*)(sm + B_HI + bb);
                uint32_t bh1 = *(const uint32_t*)(sm + B_HI + bb + 16);
                uint32_t bl0 = *(const uint32_t*)(sm + B_LO + bb);
                uint32_t bl1 = *(const uint32_t*)(sm + B_LO + bb + 16);
                #pragma unroll
                for (int mt = 0; mt < 2; mt++) {
                    mma16816(d[mt][nt], ah[mt], bh0, bh1);   // xh*wh
                    mma16816(d[mt][nt], al[mt], bh0, bh1);   // xl*wh
                    mma16816(d[mt][nt], ah[mt], bl0, bl1);   // xh*wl
                }
            }
        }
    }

    // ---- fused epilogue ----
    // thread owns rows (wm*32 + mt*16 + g) and (+8); cols wn*64 + nt*8 + (lane&3)*2 + {0,1}
    #pragma unroll
    for (int mt = 0; mt < 2; mt++) {
        float p0 = 0.f, p1 = 0.f;
        #pragma unroll
        for (int nt = 0; nt < 8; nt++) {
            int c0 = wn * 64 + nt * 8 + (lane & 3) * 2;
            float w2a = s_w2[c0],     b1a = s_b1[c0];
            float w2b = s_w2[c0 + 1], b1b = s_b1[c0 + 1];
            p0 = fmaf(fmaxf(d[mt][nt][0] + b1a, 0.f), w2a, p0);
            p0 = fmaf(fmaxf(d[mt][nt][1] + b1b, 0.f), w2b, p0);
            p1 = fmaf(fmaxf(d[mt][nt][2] + b1a, 0.f), w2a, p1);
            p1 = fmaf(fmaxf(d[mt][nt][3] + b1b, 0.f), w2b, p1);
        }
        // reduce across the 4 lanes of a row group (same g)
        p0 += __shfl_xor_sync(0xffffffffu, p0, 1);
        p0 += __shfl_xor_sync(0xffffffffu, p0, 2);
        p1 += __shfl_xor_sync(0xffffffffu, p1, 1);
        p1 += __shfl_xor_sync(0xffffffffu, p1, 2);
        if ((lane & 3) == 0) {
            int r = wm * 32 + mt * 16 + g;
            s_part[r][wn]     = p0;
            s_part[r + 8][wn] = p1;
        }
    }
    __syncthreads();

    if (tid < BM) {
        float p = s_part[tid][0] + s_part[tid][1] + s_part[tid][2] + s_part[tid][3];
        long long e = e0 + tid;
        if (e < E)
            out[e] = 1.f / (1.f + __expf(-(p + b2[0])));
    }
}

extern "C" void kernel_launch(void* const* d_in, const int* in_sizes, int n_in,
                              void* d_out, int out_size) {
    // size-based input mapping (dict order confirmed: z,src,dst,W1,b1,W2,b2)
    int idx_z = -1, idx_w1 = -1, idx_b2 = -1;
    int idx_e1 = -1, idx_e2 = -1, idx_s1 = -1, idx_s2 = -1;
    for (int i = 0; i < n_in; i++) {
        int s = in_sizes[i];
        if (s == 25600000)      idx_z = i;
        else if (s == 65536)    idx_w1 = i;
        else if (s == 1)        idx_b2 = i;
        else if (s == 1000000) { if (idx_e1 < 0) idx_e1 = i; else idx_e2 = i; }
        else if (s == 256)     { if (idx_s1 < 0) idx_s1 = i; else idx_s2 = i; }
    }
    int idx_b1 = (idx_z == 0) ? idx_s1 : idx_s2;
    int idx_w2 = (idx_z == 0) ? idx_s2 : idx_s1;

    const float* z   = (const float*)d_in[idx_z];
    const int*   src = (const int*)d_in[idx_e1];
    const int*   dst = (const int*)d_in[idx_e2];
    const float* W1  = (const float*)d_in[idx_w1];
    const float* b1  = (const float*)d_in[idx_b1];
    const float* W2  = (const float*)d_in[idx_w2];
    const float* b2  = (const float*)d_in[idx_b2];
    float* out = (float*)d_out;

    int E  = in_sizes[idx_e1];
    int Nn = in_sizes[idx_z] / INCH;

    prep_w1<<<INCH, HID>>>(W1);

    static int smem_set = 0;
    if (!smem_set) {
        cudaFuncSetAttribute(edge_decoder_hmma,
                             cudaFuncAttributeMaxDynamicSharedMemorySize, SMEM_DYN);
        smem_set = 1;
    }
    int grid = (E + BM - 1) / BM;   // 15625
    edge_decoder_hmma<<<grid, THREADS, SMEM_DYN>>>(z, src, dst, b1, W2, b2, out, E, Nn);
}